// round 13
// baseline (speedup 1.0000x reference)
#include <cuda_runtime.h>
#include <cuda_fp16.h>
#include <cstdint>

#define BATCH 1024
#define FDIM 39
#define DDIM 64
#define ODIM 128
#define KT 64
#define THREADS 256

// ---------------- scratch ----------------
__device__ alignas(16) __half g_X1[BATCH * ODIM * DDIM];
__device__ alignas(16) __half g_X2[BATCH * ODIM * DDIM];
__device__ alignas(16) __half g_W1[ODIM * 1536];
__device__ alignas(16) __half g_W2[ODIM * 4992];
__device__ alignas(16) __half g_W3[ODIM * 4992];

// ---------------- smem layout ----------------
// stage (x2): A 128x144B (18432) | B 64x144B (9216) = 27648 each
// l1:  x0h 4992 + 2*27648 = 60288
// l23: xis 8192 + 2*27648 = 63488
#define A_STRIDE 144
#define B_STRIDE 144
#define OFF_A 0
#define OFF_B 18432
#define STG_SZ 27648
#define X0H_SZ (FDIM * DDIM * 2)   // 4992
#define XIS_SZ (KT * DDIM * 2)     // 8192
#define SMEM_L1  (X0H_SZ + 2 * STG_SZ)  // 60288
#define SMEM_L23 (XIS_SZ + 2 * STG_SZ)  // 63488

__device__ __forceinline__ uint32_t smem_u32(const void* p) {
    uint32_t a;
    asm("{ .reg .u64 t; cvta.to.shared.u64 t, %1; cvt.u32.u64 %0, t; }" : "=r"(a) : "l"(p));
    return a;
}

#define CP_ASYNC16(dst, src) \
    asm volatile("cp.async.cg.shared.global [%0], [%1], 16;" :: "r"(dst), "l"(src))
#define CP_COMMIT() asm volatile("cp.async.commit_group;")
#define CP_WAIT0()  asm volatile("cp.async.wait_group 0;")

#define LDSM_X4(r, addr) \
    asm volatile("ldmatrix.sync.aligned.m8n8.x4.shared.b16 {%0,%1,%2,%3}, [%4];" \
        : "=r"((r)[0]), "=r"((r)[1]), "=r"((r)[2]), "=r"((r)[3]) : "r"(addr))
#define LDSM_X4T(r, addr) \
    asm volatile("ldmatrix.sync.aligned.m8n8.x4.trans.shared.b16 {%0,%1,%2,%3}, [%4];" \
        : "=r"((r)[0]), "=r"((r)[1]), "=r"((r)[2]), "=r"((r)[3]) : "r"(addr))

__device__ __forceinline__ void mma16816(float* c, const uint32_t* a, const uint32_t* b) {
    asm volatile("mma.sync.aligned.m16n8k16.row.col.f32.f16.f16.f32 "
        "{%0,%1,%2,%3}, {%4,%5,%6,%7}, {%8,%9}, {%0,%1,%2,%3};"
        : "+f"(c[0]), "+f"(c[1]), "+f"(c[2]), "+f"(c[3])
        : "r"(a[0]), "r"(a[1]), "r"(a[2]), "r"(a[3]), "r"(b[0]), "r"(b[1]));
}

// stage W tile: 128 rows x 128B; 2 threads/row, 64B each
template <int CPAD_>
__device__ __forceinline__ void stage_w(uint32_t sb, const __half* W, int c0, int tid) {
    const int wrow = tid >> 1, whalf = tid & 1;
    const char* src = (const char*)(W + (size_t)wrow * CPAD_ + c0) + whalf * 64;
    const uint32_t dst = sb + OFF_A + wrow * A_STRIDE + whalf * 64;
#pragma unroll
    for (int q = 0; q < 4; ++q)
        CP_ASYNC16(dst + q * 16, src + q * 16);
    CP_COMMIT();
}

// MMA over one KT=64 tile (warp tile 16o x 64n) with fused gen for next tile.
template <class GenF>
__device__ __forceinline__ void mma_tile_fused(uint32_t sb, int warp_m,
                                               int lr, int lc, float acc[8][4],
                                               GenF gen_part) {
#pragma unroll
    for (int kb = 0; kb < 4; ++kb) {
        gen_part(kb);               // independent stream: feeds buffer t+1
        uint32_t ah[4];
        const uint32_t aoff = (warp_m * 16 + lr) * A_STRIDE + kb * 32 + lc * 16;
        LDSM_X4(ah, sb + OFF_A + aoff);
#pragma unroll
        for (int ip = 0; ip < 2; ++ip) {
            uint32_t bb[2][4];
#pragma unroll
            for (int ii = 0; ii < 2; ++ii) {
                const int i = ip * 2 + ii;
                const uint32_t boff = (kb * 16 + lr) * B_STRIDE + i * 32 + lc * 16;
                LDSM_X4T(bb[ii], sb + OFF_B + boff);
            }
#pragma unroll
            for (int ii = 0; ii < 2; ++ii) {
                mma16816(acc[(ip * 2 + ii) * 2],     ah, bb[ii]);
                mma16816(acc[(ip * 2 + ii) * 2 + 1], ah, bb[ii] + 2);
            }
        }
    }
}

__device__ __forceinline__ void epilogue(float acc[8][4], const float* bias,
                                         __half* Xout, float* out, int out_off,
                                         int b, int warp_m, int lane) {
    const int r0 = warp_m * 16 + (lane >> 2);
    const int r1 = r0 + 8;
    const float bv0 = bias[r0], bv1 = bias[r1];
    float s0 = 0.f, s1 = 0.f;
#pragma unroll
    for (int nf = 0; nf < 8; ++nf) {
        float* c = acc[nf];
        s0 += c[0] + c[1];
        s1 += c[2] + c[3];
        if (Xout) {
            const int d = nf * 8 + (lane & 3) * 2;
            __half2 v0 = __floats2half2_rn(c[0] + bv0, c[1] + bv0);
            __half2 v1 = __floats2half2_rn(c[2] + bv1, c[3] + bv1);
            *(__half2*)(Xout + (size_t)b * ODIM * DDIM + r0 * DDIM + d) = v0;
            *(__half2*)(Xout + (size_t)b * ODIM * DDIM + r1 * DDIM + d) = v1;
        }
    }
    s0 += __shfl_xor_sync(0xffffffffu, s0, 1);
    s0 += __shfl_xor_sync(0xffffffffu, s0, 2);
    s1 += __shfl_xor_sync(0xffffffffu, s1, 1);
    s1 += __shfl_xor_sync(0xffffffffu, s1, 2);
    if ((lane & 3) == 0) {
        out[(size_t)b * 384 + out_off + r0] = s0 + 64.f * bv0;
        out[(size_t)b * 384 + out_off + r1] = s1 + 64.f * bv1;
    }
}

// ---------------- W convert ----------------
__global__ void conv_w_kernel(const float* __restrict__ W, __half* __restrict__ hi,
                              int C, int Cpad) {
    int i = blockIdx.x * 256 + threadIdx.x;
    if (i >= ODIM * Cpad) return;
    int o = i / Cpad, cp = i - o * Cpad;
    hi[i] = __float2half_rn((cp < C) ? W[o * C + cp] : 0.f);
}

// ---------------- Layer 1: one sample per CTA ----------------
__global__ __launch_bounds__(THREADS, 3) void cin_l1(
    const float* __restrict__ X0, const __half* __restrict__ W,
    const float* __restrict__ bias, __half* __restrict__ Xout, float* __restrict__ out)
{
    extern __shared__ char smem[];
    constexpr int CPAD_ = 1536, C_ = 1521, NT = CPAD_ / KT;   // 24 tiles

    const int tid = threadIdx.x, wid = tid >> 5, lane = tid & 31;
    const int b = blockIdx.x;
    const int warp_m = wid;
    const int lr = lane & 15, lc = lane >> 4;
    const int n2 = (tid & 31) * 2, kh = tid >> 5;   // 8 kh groups x 8 k
    const int dd = n2;

    __half* x0h = (__half*)smem;
    const uint32_t stg = smem_u32(smem + X0H_SZ);

    for (int i = tid; i < FDIM * DDIM; i += THREADS)
        x0h[i] = __float2half_rn(X0[(size_t)b * FDIM * DDIM + i]);

    float acc[8][4];
#pragma unroll
    for (int x = 0; x < 8; ++x)
#pragma unroll
        for (int y = 0; y < 4; ++y) acc[x][y] = 0.f;

    auto gen_full = [&](int t) {
        const uint32_t sb = stg + (t & 1) * STG_SZ;
        char* sbc = smem + X0H_SZ + (t & 1) * STG_SZ;
        const int c0 = t * KT;
        stage_w<CPAD_>(sb, W, c0, tid);
#pragma unroll
        for (int j = 0; j < 8; ++j) {
            const int k = kh * 8 + j;
            const int c = c0 + k;
            __half2 r = __floats2half2_rn(0.f, 0.f);
            if (c < C_) {
                const int h = c / FDIM;
                const int m = c - h * FDIM;
                r = __hmul2(*(const __half2*)(x0h + h * DDIM + dd),
                            *(const __half2*)(x0h + m * DDIM + dd));
            }
            *(__half2*)(sbc + OFF_B + k * B_STRIDE + n2 * 2) = r;
        }
    };

    __syncthreads();
    gen_full(0);
    CP_WAIT0();
    __syncthreads();

    for (int t = 0; t < NT; ++t) {
        const bool dg = (t + 1 < NT);
        const int tn = t + 1;
        const uint32_t sbn = stg + (tn & 1) * STG_SZ;
        char* sbcn = smem + X0H_SZ + (tn & 1) * STG_SZ;
        const int c0n = tn * KT;

        auto gen_part = [&](int kb) {
            if (!dg) return;
            if (kb == 0) stage_w<CPAD_>(sbn, W, c0n, tid);
            const int jb = kb * 2;
            int c = c0n + kh * 8 + jb;
            int h = c / FDIM;
            int m = c - h * FDIM;
#pragma unroll
            for (int j = 0; j < 2; ++j) {
                __half2 r = __floats2half2_rn(0.f, 0.f);
                if (c < C_)
                    r = __hmul2(*(const __half2*)(x0h + h * DDIM + dd),
                                *(const __half2*)(x0h + m * DDIM + dd));
                *(__half2*)(sbcn + OFF_B + (kh * 8 + jb + j) * B_STRIDE + n2 * 2) = r;
                ++c; ++m;
                if (m == FDIM) { m = 0; ++h; }
            }
        };

        mma_tile_fused(stg + (t & 1) * STG_SZ, warp_m, lr, lc, acc, gen_part);
        CP_WAIT0();
        __syncthreads();
    }
    epilogue(acc, bias, Xout, out, 0, b, warp_m, lane);
}

// ---------------- Layers 2/3: one sample per CTA ----------------
__global__ __launch_bounds__(THREADS, 3) void cin_l23(
    const float* __restrict__ X0, const __half* __restrict__ Xi,
    const __half* __restrict__ W,
    const float* __restrict__ bias, __half* __restrict__ Xout,
    float* __restrict__ out, int out_off)
{
    extern __shared__ char smem[];
    constexpr int CPAD_ = 4992, M_ = 128;

    const int tid = threadIdx.x, wid = tid >> 5, lane = tid & 31;
    const int b = blockIdx.x;
    const int warp_m = wid;
    const int lr = lane & 15, lc = lane >> 4;
    const int n2 = (tid & 31) * 2, kh = tid >> 5;
    const int dd = n2;

    __half* xis = (__half*)smem;
    const uint32_t stg = smem_u32(smem + XIS_SZ);
    const uint32_t xis_u32 = smem_u32(xis);
    const float* x0_row = X0 + (size_t)b * FDIM * DDIM + dd;

    float acc[8][4];
#pragma unroll
    for (int x = 0; x < 8; ++x)
#pragma unroll
        for (int y = 0; y < 4; ++y) acc[x][y] = 0.f;

    auto x0ld = [&](int h) -> float2 {
        return __ldg((const float2*)(x0_row + h * DDIM));
    };

    auto gen_full = [&](int mb, int h, int buf, float2 xf) {
        const uint32_t sb = stg + buf * STG_SZ;
        char* sbc = smem + XIS_SZ + buf * STG_SZ;
        stage_w<CPAD_>(sb, W, h * M_ + mb * KT, tid);
        const __half2 xvh = __floats2half2_rn(xf.x, xf.y);
#pragma unroll
        for (int j = 0; j < 8; ++j) {
            const int k = kh * 8 + j;
            const __half2 iv = *(const __half2*)(xis + k * DDIM + dd);
            *(__half2*)(sbc + OFF_B + k * B_STRIDE + n2 * 2) = __hmul2(xvh, iv);
        }
    };

    for (int mb = 0; mb < 2; ++mb) {
        __syncthreads();
        // stage Xi m-block (half): 64*64*2 = 8192B = 512 x 16B, 2 per thread
#pragma unroll
        for (int it = 0; it < 2; ++it) {
            const int idx = it * THREADS + tid;
            const __half* src = Xi + (size_t)b * M_ * DDIM + mb * KT * DDIM + idx * 8;
            CP_ASYNC16(xis_u32 + idx * 16, src);
        }
        CP_COMMIT();
        CP_WAIT0();
        __syncthreads();

        float2 xv0 = x0ld(0);
        gen_full(mb, 0, 0, xv0);
        float2 xv_n = x0ld(1);
        CP_WAIT0();
        __syncthreads();

        for (int h = 0; h < FDIM; ++h) {
            const bool dg = (h + 1 < FDIM);
            const int hn = h + 1;
            const uint32_t sbn = stg + (hn & 1) * STG_SZ;
            char* sbcn = smem + XIS_SZ + (hn & 1) * STG_SZ;
            const __half2 xvh = __floats2half2_rn(xv_n.x, xv_n.y);
            if (h + 2 < FDIM) xv_n = x0ld(h + 2);

            auto gen_part = [&](int kb) {
                if (!dg) return;
                if (kb == 0) stage_w<CPAD_>(sbn, W, hn * M_ + mb * KT, tid);
                const int jb = kb * 2;
#pragma unroll
                for (int j = 0; j < 2; ++j) {
                    const int k = kh * 8 + jb + j;
                    const __half2 iv = *(const __half2*)(xis + k * DDIM + dd);
                    *(__half2*)(sbcn + OFF_B + k * B_STRIDE + n2 * 2) = __hmul2(xvh, iv);
                }
            };

            mma_tile_fused(stg + (h & 1) * STG_SZ, warp_m, lr, lc, acc, gen_part);
            CP_WAIT0();
            __syncthreads();
        }
    }
    epilogue(acc, bias, Xout, out, out_off, b, warp_m, lane);
}

// ---------------- launch ----------------
extern "C" void kernel_launch(void* const* d_in, const int* in_sizes, int n_in,
                              void* d_out, int out_size)
{
    const float* X0 = (const float*)d_in[0];
    const float* W1 = (const float*)d_in[1];
    const float* b1 = (const float*)d_in[2];
    const float* W2 = (const float*)d_in[3];
    const float* b2 = (const float*)d_in[4];
    const float* W3 = (const float*)d_in[5];
    const float* b3 = (const float*)d_in[6];
    float* out = (float*)d_out;

    __half *X1p, *X2p, *W1h, *W2h, *W3h;
    cudaGetSymbolAddress((void**)&X1p, g_X1);
    cudaGetSymbolAddress((void**)&X2p, g_X2);
    cudaGetSymbolAddress((void**)&W1h, g_W1);
    cudaGetSymbolAddress((void**)&W2h, g_W2);
    cudaGetSymbolAddress((void**)&W3h, g_W3);

    cudaFuncSetAttribute(cin_l1,  cudaFuncAttributeMaxDynamicSharedMemorySize, SMEM_L1);
    cudaFuncSetAttribute(cin_l23, cudaFuncAttributeMaxDynamicSharedMemorySize, SMEM_L23);

    conv_w_kernel<<<(ODIM * 1536 + 255) / 256, 256>>>(W1, W1h, 1521, 1536);
    conv_w_kernel<<<(ODIM * 4992 + 255) / 256, 256>>>(W2, W2h, 4992, 4992);
    conv_w_kernel<<<(ODIM * 4992 + 255) / 256, 256>>>(W3, W3h, 4992, 4992);

    cin_l1 <<<BATCH, THREADS, SMEM_L1 >>>(X0, W1h, b1, X1p, out);
    cin_l23<<<BATCH, THREADS, SMEM_L23>>>(X0, X1p, W2h, b2, X2p, out, 128);
    cin_l23<<<BATCH, THREADS, SMEM_L23>>>(X0, X2p, W3h, b3, nullptr, out, 256);
}

// round 14
// speedup vs baseline: 1.3045x; 1.3045x over previous
#include <cuda_runtime.h>
#include <cuda_fp16.h>
#include <cstdint>

#define BATCH 1024
#define FDIM 39
#define DDIM 64
#define ODIM 128
#define G 2
#define KT 64
#define THREADS 256

// ---------------- scratch ----------------
__device__ alignas(16) __half g_W1[ODIM * 1536];
__device__ alignas(16) __half g_W2[ODIM * 4992];
__device__ alignas(16) __half g_W3[ODIM * 4992];

// ---------------- smem layout (bytes) ----------------
// U:   [0, 32768)      l1: x0h (2x39x64 half = 9984 used); l2/l3: Xi (2x128x64 half)
// TBL: [32768, 35840)  1536 x u16 (h<<8|m) for layer-1 c -> (h,m)
// STG: [35840, 107520) 2 stages x { A 128x144 | B 64x272 }
#define OFF_TBL 32768
#define OFF_STG 35840
#define A_STRIDE 144
#define B_STRIDE 272
#define OFF_A 0
#define OFF_B 18432
#define STG_SZ 35840
#define SMEM_TOT (OFF_STG + 2 * STG_SZ)   // 107520

__device__ __forceinline__ uint32_t smem_u32(const void* p) {
    uint32_t a;
    asm("{ .reg .u64 t; cvta.to.shared.u64 t, %1; cvt.u32.u64 %0, t; }" : "=r"(a) : "l"(p));
    return a;
}

#define CP_ASYNC16(dst, src) \
    asm volatile("cp.async.cg.shared.global [%0], [%1], 16;" :: "r"(dst), "l"(src))
#define CP_COMMIT() asm volatile("cp.async.commit_group;")
#define CP_WAIT0()  asm volatile("cp.async.wait_group 0;")

#define LDSM_X4(r, addr) \
    asm volatile("ldmatrix.sync.aligned.m8n8.x4.shared.b16 {%0,%1,%2,%3}, [%4];" \
        : "=r"((r)[0]), "=r"((r)[1]), "=r"((r)[2]), "=r"((r)[3]) : "r"(addr))
#define LDSM_X4T(r, addr) \
    asm volatile("ldmatrix.sync.aligned.m8n8.x4.trans.shared.b16 {%0,%1,%2,%3}, [%4];" \
        : "=r"((r)[0]), "=r"((r)[1]), "=r"((r)[2]), "=r"((r)[3]) : "r"(addr))

__device__ __forceinline__ void mma16816(float* c, const uint32_t* a, const uint32_t* b) {
    asm volatile("mma.sync.aligned.m16n8k16.row.col.f32.f16.f16.f32 "
        "{%0,%1,%2,%3}, {%4,%5,%6,%7}, {%8,%9}, {%0,%1,%2,%3};"
        : "+f"(c[0]), "+f"(c[1]), "+f"(c[2]), "+f"(c[3])
        : "r"(a[0]), "r"(a[1]), "r"(a[2]), "r"(a[3]), "r"(b[0]), "r"(b[1]));
}

// stage W tile: 128 rows x 128B; 2 threads/row, 64B each
template <int CPAD_>
__device__ __forceinline__ void stage_w(uint32_t sb, const __half* W, int c0, int tid) {
    const int wrow = tid >> 1, whalf = tid & 1;
    const char* src = (const char*)(W + (size_t)wrow * CPAD_ + c0) + whalf * 64;
    const uint32_t dst = sb + OFF_A + wrow * A_STRIDE + whalf * 64;
#pragma unroll
    for (int q = 0; q < 4; ++q)
        CP_ASYNC16(dst + q * 16, src + q * 16);
    CP_COMMIT();
}

// MMA over one KT=64 tile (warp tile 32o x 64n) with fused gen for next tile.
template <class GenF>
__device__ __forceinline__ void mma_tile_fused(uint32_t sb, int warp_m, int warp_n,
                                               int lr, int lc, float acc[2][8][4],
                                               GenF gen_part) {
#pragma unroll
    for (int kb = 0; kb < 4; ++kb) {
        gen_part(kb);
        uint32_t ah[2][4];
#pragma unroll
        for (int mf = 0; mf < 2; ++mf) {
            const uint32_t aoff = (warp_m * 32 + mf * 16 + lr) * A_STRIDE + kb * 32 + lc * 16;
            LDSM_X4(ah[mf], sb + OFF_A + aoff);
        }
#pragma unroll
        for (int ip = 0; ip < 2; ++ip) {
            uint32_t bb[2][4];
#pragma unroll
            for (int ii = 0; ii < 2; ++ii) {
                const int i = ip * 2 + ii;
                const uint32_t boff = (kb * 16 + lr) * B_STRIDE +
                                      (warp_n * 64 + i * 16) * 2 + lc * 16;
                LDSM_X4T(bb[ii], sb + OFF_B + boff);
            }
#pragma unroll
            for (int mf = 0; mf < 2; ++mf)
#pragma unroll
                for (int ii = 0; ii < 2; ++ii) {
                    mma16816(acc[mf][(ip * 2 + ii) * 2],     ah[mf], bb[ii]);
                    mma16816(acc[mf][(ip * 2 + ii) * 2 + 1], ah[mf], bb[ii] + 2);
                }
        }
    }
}

// epilogue: bias + pool to out; optionally write X_next into smem U (half)
__device__ __forceinline__ void epilogue_u(float acc[2][8][4], const float* bias,
                                           __half* xi_w, float* out, int out_off,
                                           int b0, int warp_m, int warp_n, int lane) {
    const int g = warp_n;
#pragma unroll
    for (int mf = 0; mf < 2; ++mf) {
        const int r0 = warp_m * 32 + mf * 16 + (lane >> 2);
        const int r1 = r0 + 8;
        const float bv0 = bias[r0], bv1 = bias[r1];
        float s0 = 0.f, s1 = 0.f;
#pragma unroll
        for (int nf = 0; nf < 8; ++nf) {
            float* c = acc[mf][nf];
            s0 += c[0] + c[1];
            s1 += c[2] + c[3];
            if (xi_w) {
                const int d = nf * 8 + (lane & 3) * 2;
                *(__half2*)(xi_w + g * 8192 + r0 * DDIM + d) =
                    __floats2half2_rn(c[0] + bv0, c[1] + bv0);
                *(__half2*)(xi_w + g * 8192 + r1 * DDIM + d) =
                    __floats2half2_rn(c[2] + bv1, c[3] + bv1);
            }
        }
        s0 += __shfl_xor_sync(0xffffffffu, s0, 1);
        s0 += __shfl_xor_sync(0xffffffffu, s0, 2);
        s1 += __shfl_xor_sync(0xffffffffu, s1, 1);
        s1 += __shfl_xor_sync(0xffffffffu, s1, 2);
        if ((lane & 3) == 0) {
            out[(size_t)(b0 + g) * 384 + out_off + r0] = s0 + 64.f * bv0;
            out[(size_t)(b0 + g) * 384 + out_off + r1] = s1 + 64.f * bv1;
        }
    }
}

// ---------------- W convert (fp32 -> fp16, zero padded) ----------------
__global__ void conv_w_kernel(const float* __restrict__ W, __half* __restrict__ hi,
                              int C, int Cpad) {
    int i = blockIdx.x * 256 + threadIdx.x;
    if (i >= ODIM * Cpad) return;
    int o = i / Cpad, cp = i - o * Cpad;
    hi[i] = __float2half_rn((cp < C) ? W[o * C + cp] : 0.f);
}

// ---------------- Fused 3-layer CIN kernel ----------------
__global__ __launch_bounds__(THREADS, 2) void cin_fused(
    const float* __restrict__ X0,
    const __half* __restrict__ W1h, const float* __restrict__ b1,
    const __half* __restrict__ W2h, const float* __restrict__ b2,
    const __half* __restrict__ W3h, const float* __restrict__ b3,
    float* __restrict__ out)
{
    extern __shared__ char smem[];
    const int tid = threadIdx.x, wid = tid >> 5, lane = tid & 31;
    const int b0 = blockIdx.x * G;
    const int warp_m = wid >> 1, warp_n = wid & 1;
    const int lr = lane & 15, lc = lane >> 4;
    const int n2 = (tid & 63) * 2, kh = tid >> 6;   // 4 kh groups x 16 k
    const int gg = n2 >> 6, dd = n2 & 63;

    __half* U = (__half*)smem;
    uint16_t* tbl = (uint16_t*)(smem + OFF_TBL);
    const uint32_t stg = smem_u32(smem + OFF_STG);

    // build (h,m) table for layer 1 + stage x0 (half) for both samples
    for (int i = tid; i < 1536; i += THREADS) {
        int h = i / FDIM, m = i - h * FDIM;
        tbl[i] = (uint16_t)((h << 8) | m);
    }
    for (int i = tid; i < G * FDIM * DDIM; i += THREADS)
        U[i] = __float2half_rn(X0[(size_t)b0 * FDIM * DDIM + i]);

    float acc[2][8][4];
#pragma unroll
    for (int a = 0; a < 2; ++a)
#pragma unroll
        for (int b = 0; b < 8; ++b)
#pragma unroll
            for (int c = 0; c < 4; ++c) acc[a][b][c] = 0.f;

    // ================= LAYER 1 =================
    {
        constexpr int CPAD_ = 1536, C_ = 1521, NT = CPAD_ / KT;  // 24 tiles
        const __half* x0_g = U + gg * FDIM * DDIM;

        auto gen_full = [&](int t) {
            const uint32_t sb = stg + (t & 1) * STG_SZ;
            char* sbc = smem + OFF_STG + (t & 1) * STG_SZ;
            const int c0 = t * KT;
            stage_w<CPAD_>(sb, W1h, c0, tid);
#pragma unroll
            for (int j = 0; j < 16; ++j) {
                const int k = kh * 16 + j;
                const int c = c0 + k;
                __half2 r = __floats2half2_rn(0.f, 0.f);
                if (c < C_) {
                    const uint32_t hm = tbl[c];
                    r = __hmul2(*(const __half2*)(x0_g + (hm >> 8) * DDIM + dd),
                                *(const __half2*)(x0_g + (hm & 255) * DDIM + dd));
                }
                *(__half2*)(sbc + OFF_B + k * B_STRIDE + n2 * 2) = r;
            }
        };

        __syncthreads();     // x0h + tbl ready
        gen_full(0);
        CP_WAIT0();
        __syncthreads();

        for (int t = 0; t < NT; ++t) {
            const bool dg = (t + 1 < NT);
            const int tn = t + 1;
            const uint32_t sbn = stg + (tn & 1) * STG_SZ;
            char* sbcn = smem + OFF_STG + (tn & 1) * STG_SZ;
            const int c0n = tn * KT;

            auto gen_part = [&](int kb) {
                if (!dg) return;
                if (kb == 0) stage_w<CPAD_>(sbn, W1h, c0n, tid);
                const int jb = kb * 4;
#pragma unroll
                for (int j = 0; j < 4; ++j) {
                    const int k = kh * 16 + jb + j;
                    const int c = c0n + k;
                    __half2 r = __floats2half2_rn(0.f, 0.f);
                    if (c < C_) {
                        const uint32_t hm = tbl[c];
                        r = __hmul2(*(const __half2*)(x0_g + (hm >> 8) * DDIM + dd),
                                    *(const __half2*)(x0_g + (hm & 255) * DDIM + dd));
                    }
                    *(__half2*)(sbcn + OFF_B + k * B_STRIDE + n2 * 2) = r;
                }
            };

            mma_tile_fused(stg + (t & 1) * STG_SZ, warp_m, warp_n, lr, lc, acc, gen_part);
            CP_WAIT0();
            __syncthreads();
        }
        // write X1 into U (x0h reads all done), pool to out
        epilogue_u(acc, b1, U, out, 0, b0, warp_m, warp_n, lane);
        __syncthreads();
    }

    // ================= LAYERS 2 & 3 =================
    const float* x0_row = X0 + (size_t)(b0 + gg) * FDIM * DDIM + dd;
    auto x0ld = [&](int h) -> float2 {
        return __ldg((const float2*)(x0_row + h * DDIM));
    };

    auto run_l23 = [&](const __half* Wp, const float* bias, bool write_xi, int out_off) {
        constexpr int CPAD_ = 4992, M_ = 128, NT = 78;   // 2 mb x 39 h
        const __half* xi_g = U + gg * 8192;

#pragma unroll
        for (int a = 0; a < 2; ++a)
#pragma unroll
            for (int b = 0; b < 8; ++b)
#pragma unroll
                for (int c = 0; c < 4; ++c) acc[a][b][c] = 0.f;

        // prologue: tile 0 = (mb0,h0)
        {
            const float2 xf = x0ld(0);
            const __half2 xvh = __floats2half2_rn(xf.x, xf.y);
            stage_w<CPAD_>(stg, Wp, 0, tid);
            char* sbc = smem + OFF_STG;
#pragma unroll
            for (int j = 0; j < 16; ++j) {
                const int k = kh * 16 + j;
                const __half2 iv = *(const __half2*)(xi_g + k * DDIM + dd);
                *(__half2*)(sbc + OFF_B + k * B_STRIDE + n2 * 2) = __hmul2(xvh, iv);
            }
        }
        float2 xv_n = x0ld(1);    // row for tile 1
        CP_WAIT0();
        __syncthreads();

        int t = 0;
        for (int mb = 0; mb < 2; ++mb) {
            for (int h = 0; h < FDIM; ++h, ++t) {
                const bool dg = (t + 1 < NT);
                const int nh  = (h + 1 < FDIM) ? h + 1 : 0;
                const int nmb = (h + 1 < FDIM) ? mb : mb + 1;
                const uint32_t sbn = stg + ((t + 1) & 1) * STG_SZ;
                char* sbcn = smem + OFF_STG + ((t + 1) & 1) * STG_SZ;
                const __half2 xvh = __floats2half2_rn(xv_n.x, xv_n.y);
                if (t + 2 < NT) {                      // prefetch x0 row of tile t+2
                    int hh = h + 2;
                    if (hh >= FDIM) hh -= FDIM;
                    xv_n = x0ld(hh);
                }

                auto gen_part = [&](int kb) {
                    if (!dg) return;
                    if (kb == 0) stage_w<CPAD_>(sbn, Wp, nh * M_ + nmb * KT, tid);
                    const int jb = kb * 4;
                    const int mbase = nmb * KT;
#pragma unroll
                    for (int j = 0; j < 4; ++j) {
                        const int k = kh * 16 + jb + j;
                        const __half2 iv = *(const __half2*)(xi_g + (mbase + k) * DDIM + dd);
                        *(__half2*)(sbcn + OFF_B + k * B_STRIDE + n2 * 2) = __hmul2(xvh, iv);
                    }
                };

                mma_tile_fused(stg + (t & 1) * STG_SZ, warp_m, warp_n, lr, lc, acc, gen_part);
                CP_WAIT0();
                __syncthreads();
            }
        }
        epilogue_u(acc, bias, write_xi ? U : nullptr, out, out_off, b0, warp_m, warp_n, lane);
        __syncthreads();
    };

    run_l23(W2h, b2, true, 128);
    run_l23(W3h, b3, false, 256);
}

// ---------------- launch ----------------
extern "C" void kernel_launch(void* const* d_in, const int* in_sizes, int n_in,
                              void* d_out, int out_size)
{
    const float* X0 = (const float*)d_in[0];
    const float* W1 = (const float*)d_in[1];
    const float* b1 = (const float*)d_in[2];
    const float* W2 = (const float*)d_in[3];
    const float* b2 = (const float*)d_in[4];
    const float* W3 = (const float*)d_in[5];
    const float* b3 = (const float*)d_in[6];
    float* out = (float*)d_out;

    __half *W1h, *W2h, *W3h;
    cudaGetSymbolAddress((void**)&W1h, g_W1);
    cudaGetSymbolAddress((void**)&W2h, g_W2);
    cudaGetSymbolAddress((void**)&W3h, g_W3);

    cudaFuncSetAttribute(cin_fused, cudaFuncAttributeMaxDynamicSharedMemorySize, SMEM_TOT);

    conv_w_kernel<<<(ODIM * 1536 + 255) / 256, 256>>>(W1, W1h, 1521, 1536);
    conv_w_kernel<<<(ODIM * 4992 + 255) / 256, 256>>>(W2, W2h, 4992, 4992);
    conv_w_kernel<<<(ODIM * 4992 + 255) / 256, 256>>>(W3, W3h, 4992, 4992);

    cin_fused<<<BATCH / G, THREADS, SMEM_TOT>>>(X0, W1h, b1, W2h, b2, W3h, b3, out);
}

// round 15
// speedup vs baseline: 1.3882x; 1.0642x over previous
#include <cuda_runtime.h>
#include <cuda_fp16.h>
#include <cstdint>

#define BATCH 1024
#define FDIM 39
#define DDIM 64
#define ODIM 128
#define G 2
#define KT 64
#define THREADS 256

// ---------------- scratch ----------------
__device__ alignas(16) __half g_X1[BATCH * ODIM * DDIM];
__device__ alignas(16) __half g_X2[BATCH * ODIM * DDIM];
__device__ alignas(16) __half g_W1[ODIM * 1536];
__device__ alignas(16) __half g_W2[ODIM * 4992];
__device__ alignas(16) __half g_W3[ODIM * 4992];

// ---------------- smem layout ----------------
// stage (x2): A 128x144B | B 64x272B = 35840 each
// l1 : x0h [0,9984) | tbl [9984,13056) | stages [13056,84736)
// l23: xis [0,32768) | stages [32768,104448)
#define A_STRIDE 144
#define B_STRIDE 272
#define OFF_A 0
#define OFF_B 18432
#define STG_SZ 35840
#define L1_TBL 9984
#define L1_STG 13056
#define L23_STG 32768
#define SMEM_L1  (L1_STG + 2 * STG_SZ)    // 84736
#define SMEM_L23 (L23_STG + 2 * STG_SZ)   // 104448

__device__ __forceinline__ uint32_t smem_u32(const void* p) {
    uint32_t a;
    asm("{ .reg .u64 t; cvta.to.shared.u64 t, %1; cvt.u32.u64 %0, t; }" : "=r"(a) : "l"(p));
    return a;
}
__device__ __forceinline__ uint32_t h2m(uint32_t a, uint32_t b) {
    __half2 r = __hmul2(*(__half2*)&a, *(__half2*)&b);
    return *(uint32_t*)&r;
}
__device__ __forceinline__ uint32_t packh2(float lo, float hi) {
    __half2 r = __floats2half2_rn(lo, hi);
    return *(uint32_t*)&r;
}

#define CP_ASYNC16(dst, src) \
    asm volatile("cp.async.cg.shared.global [%0], [%1], 16;" :: "r"(dst), "l"(src))
#define CP_COMMIT() asm volatile("cp.async.commit_group;")
#define CP_WAIT0()  asm volatile("cp.async.wait_group 0;")

#define LDSM_X4(r, addr) \
    asm volatile("ldmatrix.sync.aligned.m8n8.x4.shared.b16 {%0,%1,%2,%3}, [%4];" \
        : "=r"((r)[0]), "=r"((r)[1]), "=r"((r)[2]), "=r"((r)[3]) : "r"(addr))
#define LDSM_X4T(r, addr) \
    asm volatile("ldmatrix.sync.aligned.m8n8.x4.trans.shared.b16 {%0,%1,%2,%3}, [%4];" \
        : "=r"((r)[0]), "=r"((r)[1]), "=r"((r)[2]), "=r"((r)[3]) : "r"(addr))

__device__ __forceinline__ void mma16816(float* c, const uint32_t* a, const uint32_t* b) {
    asm volatile("mma.sync.aligned.m16n8k16.row.col.f32.f16.f16.f32 "
        "{%0,%1,%2,%3}, {%4,%5,%6,%7}, {%8,%9}, {%0,%1,%2,%3};"
        : "+f"(c[0]), "+f"(c[1]), "+f"(c[2]), "+f"(c[3])
        : "r"(a[0]), "r"(a[1]), "r"(a[2]), "r"(a[3]), "r"(b[0]), "r"(b[1]));
}

// stage W tile: 128 rows x 128B; 2 threads/row, 64B each
template <int CPAD_>
__device__ __forceinline__ void stage_w(uint32_t sb, const __half* W, int c0, int tid) {
    const int wrow = tid >> 1, whalf = tid & 1;
    const char* src = (const char*)(W + (size_t)wrow * CPAD_ + c0) + whalf * 64;
    const uint32_t dst = sb + OFF_A + wrow * A_STRIDE + whalf * 64;
#pragma unroll
    for (int q = 0; q < 4; ++q)
        CP_ASYNC16(dst + q * 16, src + q * 16);
    CP_COMMIT();
}

// MMA over one KT=64 tile: per kb, hoist all 6 LDSM, then 16 independent MMAs.
template <class GenF>
__device__ __forceinline__ void mma_tile_fused(uint32_t sb, int warp_m, int warp_n,
                                               int lr, int lc, float acc[2][8][4],
                                               GenF gen_part) {
#pragma unroll
    for (int kb = 0; kb < 4; ++kb) {
        gen_part(kb);
        uint32_t ah[2][4];
#pragma unroll
        for (int mf = 0; mf < 2; ++mf) {
            const uint32_t aoff = (warp_m * 32 + mf * 16 + lr) * A_STRIDE + kb * 32 + lc * 16;
            LDSM_X4(ah[mf], sb + OFF_A + aoff);
        }
        uint32_t bb[4][4];
#pragma unroll
        for (int i = 0; i < 4; ++i) {
            const uint32_t boff = (kb * 16 + lr) * B_STRIDE +
                                  (warp_n * 64 + i * 16) * 2 + lc * 16;
            LDSM_X4T(bb[i], sb + OFF_B + boff);
        }
#pragma unroll
        for (int i = 0; i < 4; ++i)
#pragma unroll
            for (int mf = 0; mf < 2; ++mf) {
                mma16816(acc[mf][i * 2],     ah[mf], bb[i]);
                mma16816(acc[mf][i * 2 + 1], ah[mf], bb[i] + 2);
            }
    }
}

__device__ __forceinline__ void epilogue(float acc[2][8][4], const float* bias,
                                         __half* Xout, float* out, int out_off,
                                         int b0, int warp_m, int warp_n, int lane) {
    const int g = warp_n;
#pragma unroll
    for (int mf = 0; mf < 2; ++mf) {
        const int r0 = warp_m * 32 + mf * 16 + (lane >> 2);
        const int r1 = r0 + 8;
        const float bv0 = bias[r0], bv1 = bias[r1];
        float s0 = 0.f, s1 = 0.f;
#pragma unroll
        for (int nf = 0; nf < 8; ++nf) {
            float* c = acc[mf][nf];
            s0 += c[0] + c[1];
            s1 += c[2] + c[3];
            if (Xout) {
                const int d = nf * 8 + (lane & 3) * 2;
                *(__half2*)(Xout + (size_t)(b0 + g) * ODIM * DDIM + r0 * DDIM + d) =
                    __floats2half2_rn(c[0] + bv0, c[1] + bv0);
                *(__half2*)(Xout + (size_t)(b0 + g) * ODIM * DDIM + r1 * DDIM + d) =
                    __floats2half2_rn(c[2] + bv1, c[3] + bv1);
            }
        }
        s0 += __shfl_xor_sync(0xffffffffu, s0, 1);
        s0 += __shfl_xor_sync(0xffffffffu, s0, 2);
        s1 += __shfl_xor_sync(0xffffffffu, s1, 1);
        s1 += __shfl_xor_sync(0xffffffffu, s1, 2);
        if ((lane & 3) == 0) {
            out[(size_t)(b0 + g) * 384 + out_off + r0] = s0 + 64.f * bv0;
            out[(size_t)(b0 + g) * 384 + out_off + r1] = s1 + 64.f * bv1;
        }
    }
}

// ---------------- W convert (fp32 -> fp16, zero padded) ----------------
__global__ void conv_w_kernel(const float* __restrict__ W, __half* __restrict__ hi,
                              int C, int Cpad) {
    int i = blockIdx.x * 256 + threadIdx.x;
    if (i >= ODIM * Cpad) return;
    int o = i / Cpad, cp = i - o * Cpad;
    hi[i] = __float2half_rn((cp < C) ? W[o * C + cp] : 0.f);
}

// ---------------- Layer 1 ----------------
__global__ __launch_bounds__(THREADS, 2) void cin_l1(
    const float* __restrict__ X0, const __half* __restrict__ W,
    const float* __restrict__ bias, __half* __restrict__ Xout, float* __restrict__ out)
{
    extern __shared__ char smem[];
    constexpr int CPAD_ = 1536, C_ = 1521, NT = CPAD_ / KT;   // 24 tiles

    const int tid = threadIdx.x, wid = tid >> 5, lane = tid & 31;
    const int b0 = blockIdx.x * G;
    const int warp_m = wid >> 1, warp_n = wid & 1;
    const int lr = lane & 15, lc = lane >> 4;
    // gen map: 8 consecutive n, 4 k per thread
    const int ng = (tid & 15) * 8, kg = (tid >> 4) * 4;
    const int gg = ng >> 6, d8 = ng & 63;

    __half* x0h = (__half*)smem;
    uint16_t* tbl = (uint16_t*)(smem + L1_TBL);
    const uint32_t stg = smem_u32(smem + L1_STG);
    const __half* x0_g = x0h + gg * FDIM * DDIM;

    for (int i = tid; i < 1536; i += THREADS) {
        int h = i / FDIM, m = i - h * FDIM;
        tbl[i] = (uint16_t)((h << 8) | m);
    }
    for (int i = tid; i < G * FDIM * DDIM; i += THREADS)
        x0h[i] = __float2half_rn(X0[(size_t)b0 * FDIM * DDIM + i]);

    float acc[2][8][4];
#pragma unroll
    for (int a = 0; a < 2; ++a)
#pragma unroll
        for (int b = 0; b < 8; ++b)
#pragma unroll
            for (int c = 0; c < 4; ++c) acc[a][b][c] = 0.f;

    auto genj = [&](char* sbc, int c0, int j) {
        const int k = kg + j;
        const int c = c0 + k;
        uint4 rv = make_uint4(0u, 0u, 0u, 0u);
        if (c < C_) {
            const uint32_t hm = tbl[c];
            const uint4 xa = *(const uint4*)(x0_g + (hm >> 8) * DDIM + d8);
            const uint4 xb = *(const uint4*)(x0_g + (hm & 255) * DDIM + d8);
            rv.x = h2m(xa.x, xb.x); rv.y = h2m(xa.y, xb.y);
            rv.z = h2m(xa.z, xb.z); rv.w = h2m(xa.w, xb.w);
        }
        *(uint4*)(sbc + OFF_B + k * B_STRIDE + ng * 2) = rv;
    };

    __syncthreads();   // x0h + tbl ready
    {
        stage_w<CPAD_>(stg, W, 0, tid);
        char* sbc = smem + L1_STG;
#pragma unroll
        for (int j = 0; j < 4; ++j) genj(sbc, 0, j);
    }
    CP_WAIT0();
    __syncthreads();

    for (int t = 0; t < NT; ++t) {
        const bool dg = (t + 1 < NT);
        const int c0n = (t + 1) * KT;
        const uint32_t sbn = stg + ((t + 1) & 1) * STG_SZ;
        char* sbcn = smem + L1_STG + ((t + 1) & 1) * STG_SZ;

        auto gen_part = [&](int kb) {
            if (!dg) return;
            if (kb == 0) stage_w<CPAD_>(sbn, W, c0n, tid);
            genj(sbcn, c0n, kb);
        };

        mma_tile_fused(stg + (t & 1) * STG_SZ, warp_m, warp_n, lr, lc, acc, gen_part);
        CP_WAIT0();
        __syncthreads();
    }
    epilogue(acc, bias, Xout, out, 0, b0, warp_m, warp_n, lane);
}

// ---------------- Layers 2/3: full Xi resident in smem, 78 continuous tiles ----------------
__global__ __launch_bounds__(THREADS, 2) void cin_l23(
    const float* __restrict__ X0, const __half* __restrict__ Xi,
    const __half* __restrict__ W,
    const float* __restrict__ bias, __half* __restrict__ Xout,
    float* __restrict__ out, int out_off)
{
    extern __shared__ char smem[];
    constexpr int CPAD_ = 4992, M_ = 128, NT = 78;

    const int tid = threadIdx.x, wid = tid >> 5, lane = tid & 31;
    const int b0 = blockIdx.x * G;
    const int warp_m = wid >> 1, warp_n = wid & 1;
    const int lr = lane & 15, lc = lane >> 4;
    const int ng = (tid & 15) * 8, kg = (tid >> 4) * 4;
    const int gg = ng >> 6, d8 = ng & 63;

    __half* xis = (__half*)smem;
    const uint32_t stg = smem_u32(smem + L23_STG);
    const uint32_t xis_u32 = smem_u32(xis);
    const __half* xi_g = xis + gg * 8192;
    const float* x0_row = X0 + (size_t)(b0 + gg) * FDIM * DDIM + d8;

    // stage full Xi (both samples, 32KB): 2048 x 16B chunks, 8 per thread
#pragma unroll
    for (int it = 0; it < 8; ++it) {
        const int idx = it * THREADS + tid;
        CP_ASYNC16(xis_u32 + idx * 16, Xi + (size_t)b0 * ODIM * DDIM + idx * 8);
    }
    CP_COMMIT();

    float acc[2][8][4];
#pragma unroll
    for (int a = 0; a < 2; ++a)
#pragma unroll
        for (int b = 0; b < 8; ++b)
#pragma unroll
            for (int c = 0; c < 4; ++c) acc[a][b][c] = 0.f;

    auto x0ld = [&](int h, float4& f0, float4& f1) {
        f0 = __ldg((const float4*)(x0_row + h * DDIM));
        f1 = __ldg((const float4*)(x0_row + h * DDIM + 4));
    };

    CP_WAIT0();          // xis resident
    __syncthreads();

    // prologue: tile 0 = (mb0, h0)
    float4 xf0, xf1;
    {
        x0ld(0, xf0, xf1);
        uint32_t xw[4] = { packh2(xf0.x, xf0.y), packh2(xf0.z, xf0.w),
                           packh2(xf1.x, xf1.y), packh2(xf1.z, xf1.w) };
        stage_w<CPAD_>(stg, W, 0, tid);
        char* sbc = smem + L23_STG;
#pragma unroll
        for (int j = 0; j < 4; ++j) {
            const int k = kg + j;
            const uint4 iv = *(const uint4*)(xi_g + k * DDIM + d8);
            uint4 rv;
            rv.x = h2m(xw[0], iv.x); rv.y = h2m(xw[1], iv.y);
            rv.z = h2m(xw[2], iv.z); rv.w = h2m(xw[3], iv.w);
            *(uint4*)(sbc + OFF_B + k * B_STRIDE + ng * 2) = rv;
        }
    }
    x0ld(1, xf0, xf1);   // x0 row for tile 1
    CP_WAIT0();
    __syncthreads();

    int t = 0;
    for (int mb = 0; mb < 2; ++mb) {
        for (int h = 0; h < FDIM; ++h, ++t) {
            const bool dg = (t + 1 < NT);
            const int nh  = (h + 1 < FDIM) ? h + 1 : 0;
            const int nmb = (h + 1 < FDIM) ? mb : mb + 1;
            const uint32_t sbn = stg + ((t + 1) & 1) * STG_SZ;
            char* sbcn = smem + L23_STG + ((t + 1) & 1) * STG_SZ;
            const uint32_t xw[4] = { packh2(xf0.x, xf0.y), packh2(xf0.z, xf0.w),
                                     packh2(xf1.x, xf1.y), packh2(xf1.z, xf1.w) };
            if (t + 2 < NT) {
                int hh = h + 2;
                if (hh >= FDIM) hh -= FDIM;
                x0ld(hh, xf0, xf1);
            }
            const int mbase = nmb * KT;

            auto gen_part = [&](int kb) {
                if (!dg) return;
                if (kb == 0) stage_w<CPAD_>(sbn, W, nh * M_ + nmb * KT, tid);
                const int k = kg + kb;
                const uint4 iv = *(const uint4*)(xi_g + (mbase + k) * DDIM + d8);
                uint4 rv;
                rv.x = h2m(xw[0], iv.x); rv.y = h2m(xw[1], iv.y);
                rv.z = h2m(xw[2], iv.z); rv.w = h2m(xw[3], iv.w);
                *(uint4*)(sbcn + OFF_B + k * B_STRIDE + ng * 2) = rv;
            };

            mma_tile_fused(stg + (t & 1) * STG_SZ, warp_m, warp_n, lr, lc, acc, gen_part);
            CP_WAIT0();
            __syncthreads();
        }
    }
    epilogue(acc, bias, Xout, out, out_off, b0, warp_m, warp_n, lane);
}

// ---------------- launch ----------------
extern "C" void kernel_launch(void* const* d_in, const int* in_sizes, int n_in,
                              void* d_out, int out_size)
{
    const float* X0 = (const float*)d_in[0];
    const float* W1 = (const float*)d_in[1];
    const float* b1 = (const float*)d_in[2];
    const float* W2 = (const float*)d_in[3];
    const float* b2 = (const float*)d_in[4];
    const float* W3 = (const float*)d_in[5];
    const float* b3 = (const float*)d_in[6];
    float* out = (float*)d_out;

    __half *X1p, *X2p, *W1h, *W2h, *W3h;
    cudaGetSymbolAddress((void**)&X1p, g_X1);
    cudaGetSymbolAddress((void**)&X2p, g_X2);
    cudaGetSymbolAddress((void**)&W1h, g_W1);
    cudaGetSymbolAddress((void**)&W2h, g_W2);
    cudaGetSymbolAddress((void**)&W3h, g_W3);

    cudaFuncSetAttribute(cin_l1,  cudaFuncAttributeMaxDynamicSharedMemorySize, SMEM_L1);
    cudaFuncSetAttribute(cin_l23, cudaFuncAttributeMaxDynamicSharedMemorySize, SMEM_L23);

    conv_w_kernel<<<(ODIM * 1536 + 255) / 256, 256>>>(W1, W1h, 1521, 1536);
    conv_w_kernel<<<(ODIM * 4992 + 255) / 256, 256>>>(W2, W2h, 4992, 4992);
    conv_w_kernel<<<(ODIM * 4992 + 255) / 256, 256>>>(W3, W3h, 4992, 4992);

    cin_l1 <<<BATCH / G, THREADS, SMEM_L1 >>>(X0, W1h, b1, X1p, out);
    cin_l23<<<BATCH / G, THREADS, SMEM_L23>>>(X0, X1p, W2h, b2, X2p, out, 128);
    cin_l23<<<BATCH / G, THREADS, SMEM_L23>>>(X0, X2p, W3h, b3, nullptr, out, 256);
}

// round 16
// speedup vs baseline: 1.4007x; 1.0090x over previous
#include <cuda_runtime.h>
#include <cuda_fp16.h>
#include <cstdint>

#define BATCH 1024
#define FDIM 39
#define DDIM 64
#define ODIM 128
#define G 2
#define KT 64
#define THREADS 256

// ---------------- scratch ----------------
__device__ alignas(16) __half g_X1[BATCH * ODIM * DDIM];
__device__ alignas(16) __half g_X2[BATCH * ODIM * DDIM];
__device__ alignas(16) __half g_W1[ODIM * 1536];
__device__ alignas(16) __half g_W2[ODIM * 4992];
__device__ alignas(16) __half g_W3[ODIM * 4992];

// ---------------- smem layout ----------------
#define A_STRIDE 144
#define B_STRIDE 272
#define OFF_A 0
#define OFF_B 18432
#define STG_SZ 35840
#define L1_TBL 9984
#define L1_STG 13056
#define L23_STG 32768
#define SMEM_L1  (L1_STG + 2 * STG_SZ)    // 84736
#define SMEM_L23 (L23_STG + 2 * STG_SZ)   // 104448

__device__ __forceinline__ uint32_t smem_u32(const void* p) {
    uint32_t a;
    asm("{ .reg .u64 t; cvta.to.shared.u64 t, %1; cvt.u32.u64 %0, t; }" : "=r"(a) : "l"(p));
    return a;
}
__device__ __forceinline__ uint32_t h2m(uint32_t a, uint32_t b) {
    __half2 r = __hmul2(*(__half2*)&a, *(__half2*)&b);
    return *(uint32_t*)&r;
}
__device__ __forceinline__ uint32_t packh2(float lo, float hi) {
    __half2 r = __floats2half2_rn(lo, hi);
    return *(uint32_t*)&r;
}

#define CP_ASYNC16(dst, src) \
    asm volatile("cp.async.cg.shared.global [%0], [%1], 16;" :: "r"(dst), "l"(src))
#define CP_COMMIT() asm volatile("cp.async.commit_group;")
#define CP_WAIT0()  asm volatile("cp.async.wait_group 0;")

#define LDSM_X4(r, addr) \
    asm volatile("ldmatrix.sync.aligned.m8n8.x4.shared.b16 {%0,%1,%2,%3}, [%4];" \
        : "=r"((r)[0]), "=r"((r)[1]), "=r"((r)[2]), "=r"((r)[3]) : "r"(addr))
#define LDSM_X4T(r, addr) \
    asm volatile("ldmatrix.sync.aligned.m8n8.x4.trans.shared.b16 {%0,%1,%2,%3}, [%4];" \
        : "=r"((r)[0]), "=r"((r)[1]), "=r"((r)[2]), "=r"((r)[3]) : "r"(addr))

__device__ __forceinline__ void mma16816(float* c, const uint32_t* a, const uint32_t* b) {
    asm volatile("mma.sync.aligned.m16n8k16.row.col.f32.f16.f16.f32 "
        "{%0,%1,%2,%3}, {%4,%5,%6,%7}, {%8,%9}, {%0,%1,%2,%3};"
        : "+f"(c[0]), "+f"(c[1]), "+f"(c[2]), "+f"(c[3])
        : "r"(a[0]), "r"(a[1]), "r"(a[2]), "r"(a[3]), "r"(b[0]), "r"(b[1]));
}

// stage W tile: 128 rows x 128B; 2 threads/row, 64B each
template <int CPAD_>
__device__ __forceinline__ void stage_w(uint32_t sb, const __half* W, int c0, int tid) {
    const int wrow = tid >> 1, whalf = tid & 1;
    const char* src = (const char*)(W + (size_t)wrow * CPAD_ + c0) + whalf * 64;
    const uint32_t dst = sb + OFF_A + wrow * A_STRIDE + whalf * 64;
#pragma unroll
    for (int q = 0; q < 4; ++q)
        CP_ASYNC16(dst + q * 16, src + q * 16);
    CP_COMMIT();
}

// MMA over one KT=64 tile. A-fragments software-pipelined one kb ahead.
template <class GenF>
__device__ __forceinline__ void mma_tile_fused(uint32_t sb, int warp_m, int warp_n,
                                               int lr, int lc, float acc[2][8][4],
                                               GenF gen_part) {
    const uint32_t abase = sb + OFF_A + (warp_m * 32 + lr) * A_STRIDE + lc * 16;
    uint32_t ah[2][4];
    LDSM_X4(ah[0], abase);
    LDSM_X4(ah[1], abase + 16 * A_STRIDE);
#pragma unroll
    for (int kb = 0; kb < 4; ++kb) {
        gen_part(kb);
        uint32_t bb[4][4];
#pragma unroll
        for (int i = 0; i < 4; ++i) {
            const uint32_t boff = (kb * 16 + lr) * B_STRIDE +
                                  (warp_n * 64 + i * 16) * 2 + lc * 16;
            LDSM_X4T(bb[i], sb + OFF_B + boff);
        }
        uint32_t an[2][4];
        if (kb < 3) {
            LDSM_X4(an[0], abase + (kb + 1) * 32);
            LDSM_X4(an[1], abase + (kb + 1) * 32 + 16 * A_STRIDE);
        }
#pragma unroll
        for (int i = 0; i < 4; ++i)
#pragma unroll
            for (int mf = 0; mf < 2; ++mf) {
                mma16816(acc[mf][i * 2],     ah[mf], bb[i]);
                mma16816(acc[mf][i * 2 + 1], ah[mf], bb[i] + 2);
            }
        if (kb < 3) {
#pragma unroll
            for (int mf = 0; mf < 2; ++mf)
#pragma unroll
                for (int q = 0; q < 4; ++q) ah[mf][q] = an[mf][q];
        }
    }
}

__device__ __forceinline__ void epilogue(float acc[2][8][4], const float* bias,
                                         __half* Xout, float* out, int out_off,
                                         int b0, int warp_m, int warp_n, int lane) {
    const int g = warp_n;
#pragma unroll
    for (int mf = 0; mf < 2; ++mf) {
        const int r0 = warp_m * 32 + mf * 16 + (lane >> 2);
        const int r1 = r0 + 8;
        const float bv0 = bias[r0], bv1 = bias[r1];
        float s0 = 0.f, s1 = 0.f;
#pragma unroll
        for (int nf = 0; nf < 8; ++nf) {
            float* c = acc[mf][nf];
            s0 += c[0] + c[1];
            s1 += c[2] + c[3];
            if (Xout) {
                const int d = nf * 8 + (lane & 3) * 2;
                *(__half2*)(Xout + (size_t)(b0 + g) * ODIM * DDIM + r0 * DDIM + d) =
                    __floats2half2_rn(c[0] + bv0, c[1] + bv0);
                *(__half2*)(Xout + (size_t)(b0 + g) * ODIM * DDIM + r1 * DDIM + d) =
                    __floats2half2_rn(c[2] + bv1, c[3] + bv1);
            }
        }
        s0 += __shfl_xor_sync(0xffffffffu, s0, 1);
        s0 += __shfl_xor_sync(0xffffffffu, s0, 2);
        s1 += __shfl_xor_sync(0xffffffffu, s1, 1);
        s1 += __shfl_xor_sync(0xffffffffu, s1, 2);
        if ((lane & 3) == 0) {
            out[(size_t)(b0 + g) * 384 + out_off + r0] = s0 + 64.f * bv0;
            out[(size_t)(b0 + g) * 384 + out_off + r1] = s1 + 64.f * bv1;
        }
    }
}

// ---------------- W convert (fp32 -> fp16, zero padded) ----------------
__global__ void conv_w_kernel(const float* __restrict__ W, __half* __restrict__ hi,
                              int C, int Cpad) {
    int i = blockIdx.x * 256 + threadIdx.x;
    if (i >= ODIM * Cpad) return;
    int o = i / Cpad, cp = i - o * Cpad;
    hi[i] = __float2half_rn((cp < C) ? W[o * C + cp] : 0.f);
}

// ---------------- Layer 1 ----------------
__global__ __launch_bounds__(THREADS, 2) void cin_l1(
    const float* __restrict__ X0, const __half* __restrict__ W,
    const float* __restrict__ bias, __half* __restrict__ Xout, float* __restrict__ out)
{
    extern __shared__ char smem[];
    constexpr int CPAD_ = 1536, C_ = 1521, NT = CPAD_ / KT;   // 24 tiles; 0..22 full

    const int tid = threadIdx.x, wid = tid >> 5, lane = tid & 31;
    const int b0 = blockIdx.x * G;
    const int warp_m = wid >> 1, warp_n = wid & 1;
    const int lr = lane & 15, lc = lane >> 4;
    const int ng = (tid & 15) * 8, kg = (tid >> 4) * 4;
    const int gg = ng >> 6, d8 = ng & 63;

    __half* x0h = (__half*)smem;
    uint16_t* tbl = (uint16_t*)(smem + L1_TBL);
    const uint32_t stg = smem_u32(smem + L1_STG);
    const __half* x0_g = x0h + gg * FDIM * DDIM;

    for (int i = tid; i < 1536; i += THREADS) {
        int h = i / FDIM, m = i - h * FDIM;
        tbl[i] = (uint16_t)((h << 8) | m);
    }
    for (int i = tid; i < G * FDIM * DDIM; i += THREADS)
        x0h[i] = __float2half_rn(X0[(size_t)b0 * FDIM * DDIM + i]);

    float acc[2][8][4];
#pragma unroll
    for (int a = 0; a < 2; ++a)
#pragma unroll
        for (int b = 0; b < 8; ++b)
#pragma unroll
            for (int c = 0; c < 4; ++c) acc[a][b][c] = 0.f;

    // branchless gen for full tiles (all c < C_)
    auto genj_full = [&](char* sbc, int c0, int j) {
        const int k = kg + j;
        const uint32_t hm = tbl[c0 + k];
        const uint4 xa = *(const uint4*)(x0_g + (hm >> 8) * DDIM + d8);
        const uint4 xb = *(const uint4*)(x0_g + (hm & 255) * DDIM + d8);
        uint4 rv;
        rv.x = h2m(xa.x, xb.x); rv.y = h2m(xa.y, xb.y);
        rv.z = h2m(xa.z, xb.z); rv.w = h2m(xa.w, xb.w);
        *(uint4*)(sbc + OFF_B + k * B_STRIDE + ng * 2) = rv;
    };
    auto genj_tail = [&](char* sbc, int c0, int j) {
        const int k = kg + j;
        const int c = c0 + k;
        uint4 rv = make_uint4(0u, 0u, 0u, 0u);
        if (c < C_) {
            const uint32_t hm = tbl[c];
            const uint4 xa = *(const uint4*)(x0_g + (hm >> 8) * DDIM + d8);
            const uint4 xb = *(const uint4*)(x0_g + (hm & 255) * DDIM + d8);
            rv.x = h2m(xa.x, xb.x); rv.y = h2m(xa.y, xb.y);
            rv.z = h2m(xa.z, xb.z); rv.w = h2m(xa.w, xb.w);
        }
        *(uint4*)(sbc + OFF_B + k * B_STRIDE + ng * 2) = rv;
    };

    __syncthreads();   // x0h + tbl ready
    {
        stage_w<CPAD_>(stg, W, 0, tid);
        char* sbc = smem + L1_STG;
#pragma unroll
        for (int j = 0; j < 4; ++j) genj_full(sbc, 0, j);
    }
    CP_WAIT0();
    __syncthreads();

    for (int t = 0; t < NT; ++t) {
        const int tn = t + 1;
        const bool dg = (tn < NT);
        const bool tail = (tn == NT - 1);
        const int c0n = tn * KT;
        const uint32_t sbn = stg + (tn & 1) * STG_SZ;
        char* sbcn = smem + L1_STG + (tn & 1) * STG_SZ;

        auto gen_part = [&](int kb) {
            if (!dg) return;
            if (kb == 0) stage_w<CPAD_>(sbn, W, c0n, tid);
            if (tail) genj_tail(sbcn, c0n, kb);
            else      genj_full(sbcn, c0n, kb);
        };

        mma_tile_fused(stg + (t & 1) * STG_SZ, warp_m, warp_n, lr, lc, acc, gen_part);
        CP_WAIT0();
        __syncthreads();
    }
    epilogue(acc, bias, Xout, out, 0, b0, warp_m, warp_n, lane);
}

// ---------------- Layers 2/3 ----------------
__global__ __launch_bounds__(THREADS, 2) void cin_l23(
    const float* __restrict__ X0, const __half* __restrict__ Xi,
    const __half* __restrict__ W,
    const float* __restrict__ bias, __half* __restrict__ Xout,
    float* __restrict__ out, int out_off)
{
    extern __shared__ char smem[];
    constexpr int CPAD_ = 4992, M_ = 128, NT = 78;

    const int tid = threadIdx.x, wid = tid >> 5, lane = tid & 31;
    const int b0 = blockIdx.x * G;
    const int warp_m = wid >> 1, warp_n = wid & 1;
    const int lr = lane & 15, lc = lane >> 4;
    const int ng = (tid & 15) * 8, kg = (tid >> 4) * 4;
    const int gg = ng >> 6, d8 = ng & 63;

    __half* xis = (__half*)smem;
    const uint32_t stg = smem_u32(smem + L23_STG);
    const uint32_t xis_u32 = smem_u32(xis);
    const __half* xi_g = xis + gg * 8192;
    const float* x0_row = X0 + (size_t)(b0 + gg) * FDIM * DDIM + d8;

#pragma unroll
    for (int it = 0; it < 8; ++it) {
        const int idx = it * THREADS + tid;
        CP_ASYNC16(xis_u32 + idx * 16, Xi + (size_t)b0 * ODIM * DDIM + idx * 8);
    }
    CP_COMMIT();

    float acc[2][8][4];
#pragma unroll
    for (int a = 0; a < 2; ++a)
#pragma unroll
        for (int b = 0; b < 8; ++b)
#pragma unroll
            for (int c = 0; c < 4; ++c) acc[a][b][c] = 0.f;

    auto x0ld = [&](int h, float4& f0, float4& f1) {
        f0 = __ldg((const float4*)(x0_row + h * DDIM));
        f1 = __ldg((const float4*)(x0_row + h * DDIM + 4));
    };

    CP_WAIT0();
    __syncthreads();

    float4 xf0, xf1;
    {
        x0ld(0, xf0, xf1);
        uint32_t xw[4] = { packh2(xf0.x, xf0.y), packh2(xf0.z, xf0.w),
                           packh2(xf1.x, xf1.y), packh2(xf1.z, xf1.w) };
        stage_w<CPAD_>(stg, W, 0, tid);
        char* sbc = smem + L23_STG;
#pragma unroll
        for (int j = 0; j < 4; ++j) {
            const int k = kg + j;
            const uint4 iv = *(const uint4*)(xi_g + k * DDIM + d8);
            uint4 rv;
            rv.x = h2m(xw[0], iv.x); rv.y = h2m(xw[1], iv.y);
            rv.z = h2m(xw[2], iv.z); rv.w = h2m(xw[3], iv.w);
            *(uint4*)(sbc + OFF_B + k * B_STRIDE + ng * 2) = rv;
        }
    }
    x0ld(1, xf0, xf1);
    CP_WAIT0();
    __syncthreads();

    int t = 0;
    for (int mb = 0; mb < 2; ++mb) {
        for (int h = 0; h < FDIM; ++h, ++t) {
            const bool dg = (t + 1 < NT);
            const int nh  = (h + 1 < FDIM) ? h + 1 : 0;
            const int nmb = (h + 1 < FDIM) ? mb : mb + 1;
            const uint32_t sbn = stg + ((t + 1) & 1) * STG_SZ;
            char* sbcn = smem + L23_STG + ((t + 1) & 1) * STG_SZ;
            const uint32_t xw[4] = { packh2(xf0.x, xf0.y), packh2(xf0.z, xf0.w),
                                     packh2(xf1.x, xf1.y), packh2(xf1.z, xf1.w) };
            if (t + 2 < NT) {
                int hh = h + 2;
                if (hh >= FDIM) hh -= FDIM;
                x0ld(hh, xf0, xf1);
            }
            const int mbase = nmb * KT;

            auto gen_part = [&](int kb) {
                if (!dg) return;
                if (kb == 0) stage_w<CPAD_>(sbn, W, nh * M_ + nmb * KT, tid);
                const int k = kg + kb;
                const uint4 iv = *(const uint4*)(xi_g + (mbase + k) * DDIM + d8);
                uint4 rv;
                rv.x = h2m(xw[0], iv.x); rv.y = h2m(xw[1], iv.y);
                rv.z = h2m(xw[2], iv.z); rv.w = h2m(xw[3], iv.w);
                *(uint4*)(sbcn + OFF_B + k * B_STRIDE + ng * 2) = rv;
            };

            mma_tile_fused(stg + (t & 1) * STG_SZ, warp_m, warp_n, lr, lc, acc, gen_part);
            CP_WAIT0();
            __syncthreads();
        }
    }
    epilogue(acc, bias, Xout, out, out_off, b0, warp_m, warp_n, lane);
}

// ---------------- launch ----------------
extern "C" void kernel_launch(void* const* d_in, const int* in_sizes, int n_in,
                              void* d_out, int out_size)
{
    const float* X0 = (const float*)d_in[0];
    const float* W1 = (const float*)d_in[1];
    const float* b1 = (const float*)d_in[2];
    const float* W2 = (const float*)d_in[3];
    const float* b2 = (const float*)d_in[4];
    const float* W3 = (const float*)d_in[5];
    const float* b3 = (const float*)d_in[6];
    float* out = (float*)d_out;

    __half *X1p, *X2p, *W1h, *W2h, *W3h;
    cudaGetSymbolAddress((void**)&X1p, g_X1);
    cudaGetSymbolAddress((void**)&X2p, g_X2);
    cudaGetSymbolAddress((void**)&W1h, g_W1);
    cudaGetSymbolAddress((void**)&W2h, g_W2);
    cudaGetSymbolAddress((void**)&W3h, g_W3);

    cudaFuncSetAttribute(cin_l1,  cudaFuncAttributeMaxDynamicSharedMemorySize, SMEM_L1);
    cudaFuncSetAttribute(cin_l23, cudaFuncAttributeMaxDynamicSharedMemorySize, SMEM_L23);

    conv_w_kernel<<<(ODIM * 1536 + 255) / 256, 256>>>(W1, W1h, 1521, 1536);
    conv_w_kernel<<<(ODIM * 4992 + 255) / 256, 256>>>(W2, W2h, 4992, 4992);
    conv_w_kernel<<<(ODIM * 4992 + 255) / 256, 256>>>(W3, W3h, 4992, 4992);

    cin_l1 <<<BATCH / G, THREADS, SMEM_L1 >>>(X0, W1h, b1, X1p, out);
    cin_l23<<<BATCH / G, THREADS, SMEM_L23>>>(X0, X1p, W2h, b2, X2p, out, 128);
    cin_l23<<<BATCH / G, THREADS, SMEM_L23>>>(X0, X2p, W3h, b3, nullptr, out, 256);
}

// round 17
// speedup vs baseline: 1.4815x; 1.0577x over previous
#include <cuda_runtime.h>
#include <cuda_fp16.h>
#include <cstdint>

#define BATCH 1024
#define FDIM 39
#define DDIM 64
#define ODIM 128
#define G 2
#define KT 64
#define THREADS 256

// ---------------- scratch ----------------
__device__ alignas(16) __half g_X1[BATCH * ODIM * DDIM];
__device__ alignas(16) __half g_X2[BATCH * ODIM * DDIM];
__device__ alignas(16) __half g_W1[ODIM * 1536];
__device__ alignas(16) __half g_W2[ODIM * 4992];
__device__ alignas(16) __half g_W3[ODIM * 4992];

// ---------------- smem layout (swizzled, unpadded) ----------------
// A buffer: 128 rows x 128B (SWZ128) = 16384 ; B buffer: 64 rows x 256B (SWZ256) = 16384
// l1 : x0h [0,9984) | tbl [9984,13056) | A0 A1 | B0 B1 B2     = 94976
// l23: xis [0,32768) | A0 A1 | B0 B1 B2                        = 114688
#define AS_SZ 16384
#define BS_SZ 16384
#define L1_TBL 9984
#define L1_A   13056
#define L1_B   (L1_A + 2 * AS_SZ)
#define SMEM_L1  (L1_B + 3 * BS_SZ)     // 94976
#define L23_A  32768
#define L23_B  (L23_A + 2 * AS_SZ)
#define SMEM_L23 (L23_B + 3 * BS_SZ)    // 114688

#define SWZ128(o) ((o) ^ (((o) >> 3) & 0x70))
#define SWZ256(o) ((o) ^ (((o) >> 4) & 0x70))

__device__ __forceinline__ uint32_t smem_u32(const void* p) {
    uint32_t a;
    asm("{ .reg .u64 t; cvta.to.shared.u64 t, %1; cvt.u32.u64 %0, t; }" : "=r"(a) : "l"(p));
    return a;
}
__device__ __forceinline__ uint32_t h2m(uint32_t a, uint32_t b) {
    __half2 r = __hmul2(*(__half2*)&a, *(__half2*)&b);
    return *(uint32_t*)&r;
}
__device__ __forceinline__ uint32_t packh2(float lo, float hi) {
    __half2 r = __floats2half2_rn(lo, hi);
    return *(uint32_t*)&r;
}

#define CP_ASYNC16(dst, src) \
    asm volatile("cp.async.cg.shared.global [%0], [%1], 16;" :: "r"(dst), "l"(src))
#define CP_COMMIT() asm volatile("cp.async.commit_group;")
#define CP_WAIT0()  asm volatile("cp.async.wait_group 0;")

#define LDSM_X4(r, addr) \
    asm volatile("ldmatrix.sync.aligned.m8n8.x4.shared.b16 {%0,%1,%2,%3}, [%4];" \
        : "=r"((r)[0]), "=r"((r)[1]), "=r"((r)[2]), "=r"((r)[3]) : "r"(addr))
#define LDSM_X4T(r, addr) \
    asm volatile("ldmatrix.sync.aligned.m8n8.x4.trans.shared.b16 {%0,%1,%2,%3}, [%4];" \
        : "=r"((r)[0]), "=r"((r)[1]), "=r"((r)[2]), "=r"((r)[3]) : "r"(addr))

__device__ __forceinline__ void mma16816(float* c, const uint32_t* a, const uint32_t* b) {
    asm volatile("mma.sync.aligned.m16n8k16.row.col.f32.f16.f16.f32 "
        "{%0,%1,%2,%3}, {%4,%5,%6,%7}, {%8,%9}, {%0,%1,%2,%3};"
        : "+f"(c[0]), "+f"(c[1]), "+f"(c[2]), "+f"(c[3])
        : "r"(a[0]), "r"(a[1]), "r"(a[2]), "r"(a[3]), "r"(b[0]), "r"(b[1]));
}

// stage W tile into swizzled A buffer: 2 threads/row, 64B each
template <int CPAD_>
__device__ __forceinline__ void stage_w(uint32_t abuf, const __half* W, int c0, int tid) {
    const int wrow = tid >> 1, whalf = tid & 1;
    const char* src = (const char*)(W + (size_t)wrow * CPAD_ + c0) + whalf * 64;
#pragma unroll
    for (int q = 0; q < 4; ++q) {
        const uint32_t off = wrow * 128 + whalf * 64 + q * 16;
        CP_ASYNC16(abuf + SWZ128(off), src + q * 16);
    }
    CP_COMMIT();
}

// MMA over one KT=64 tile; swizzled addressing; A pipelined one kb ahead.
template <class GenF>
__device__ __forceinline__ void mma_tile_fused(uint32_t abuf, uint32_t bbuf,
                                               int warp_m, int warp_n,
                                               int lr, int lc, float acc[2][8][4],
                                               GenF gen_part) {
    const uint32_t arow0 = (warp_m * 32 + lr) * 128 + lc * 16;
    uint32_t ah[2][4];
    LDSM_X4(ah[0], abuf + SWZ128(arow0));
    LDSM_X4(ah[1], abuf + SWZ128(arow0 + 16 * 128));
#pragma unroll
    for (int kb = 0; kb < 4; ++kb) {
        gen_part(kb);
        uint32_t bb[4][4];
#pragma unroll
        for (int i = 0; i < 4; ++i) {
            const uint32_t boff = (kb * 16 + lr) * 256 +
                                  (warp_n * 64 + i * 16) * 2 + lc * 16;
            LDSM_X4T(bb[i], bbuf + SWZ256(boff));
        }
        uint32_t an[2][4];
        if (kb < 3) {
            LDSM_X4(an[0], abuf + SWZ128(arow0 + (kb + 1) * 32));
            LDSM_X4(an[1], abuf + SWZ128(arow0 + (kb + 1) * 32 + 16 * 128));
        }
#pragma unroll
        for (int i = 0; i < 4; ++i)
#pragma unroll
            for (int mf = 0; mf < 2; ++mf) {
                mma16816(acc[mf][i * 2],     ah[mf], bb[i]);
                mma16816(acc[mf][i * 2 + 1], ah[mf], bb[i] + 2);
            }
        if (kb < 3) {
#pragma unroll
            for (int mf = 0; mf < 2; ++mf)
#pragma unroll
                for (int q = 0; q < 4; ++q) ah[mf][q] = an[mf][q];
        }
    }
}

__device__ __forceinline__ void epilogue(float acc[2][8][4], const float* bias,
                                         __half* Xout, float* out, int out_off,
                                         int b0, int warp_m, int warp_n, int lane) {
    const int g = warp_n;
#pragma unroll
    for (int mf = 0; mf < 2; ++mf) {
        const int r0 = warp_m * 32 + mf * 16 + (lane >> 2);
        const int r1 = r0 + 8;
        const float bv0 = bias[r0], bv1 = bias[r1];
        float s0 = 0.f, s1 = 0.f;
#pragma unroll
        for (int nf = 0; nf < 8; ++nf) {
            float* c = acc[mf][nf];
            s0 += c[0] + c[1];
            s1 += c[2] + c[3];
            if (Xout) {
                const int d = nf * 8 + (lane & 3) * 2;
                *(__half2*)(Xout + (size_t)(b0 + g) * ODIM * DDIM + r0 * DDIM + d) =
                    __floats2half2_rn(c[0] + bv0, c[1] + bv0);
                *(__half2*)(Xout + (size_t)(b0 + g) * ODIM * DDIM + r1 * DDIM + d) =
                    __floats2half2_rn(c[2] + bv1, c[3] + bv1);
            }
        }
        s0 += __shfl_xor_sync(0xffffffffu, s0, 1);
        s0 += __shfl_xor_sync(0xffffffffu, s0, 2);
        s1 += __shfl_xor_sync(0xffffffffu, s1, 1);
        s1 += __shfl_xor_sync(0xffffffffu, s1, 2);
        if ((lane & 3) == 0) {
            out[(size_t)(b0 + g) * 384 + out_off + r0] = s0 + 64.f * bv0;
            out[(size_t)(b0 + g) * 384 + out_off + r1] = s1 + 64.f * bv1;
        }
    }
}

// ---------------- W convert (fp32 -> fp16, zero padded) ----------------
__global__ void conv_w_kernel(const float* __restrict__ W, __half* __restrict__ hi,
                              int C, int Cpad) {
    int i = blockIdx.x * 256 + threadIdx.x;
    if (i >= ODIM * Cpad) return;
    int o = i / Cpad, cp = i - o * Cpad;
    hi[i] = __float2half_rn((cp < C) ? W[o * C + cp] : 0.f);
}

// ---------------- Layer 1 ----------------
__global__ __launch_bounds__(THREADS, 2) void cin_l1(
    const float* __restrict__ X0, const __half* __restrict__ W,
    const float* __restrict__ bias, __half* __restrict__ Xout, float* __restrict__ out)
{
    extern __shared__ char smem[];
    constexpr int CPAD_ = 1536, C_ = 1521, NT = CPAD_ / KT;   // 24 tiles

    const int tid = threadIdx.x, wid = tid >> 5, lane = tid & 31;
    const int b0 = blockIdx.x * G;
    const int warp_m = wid >> 1, warp_n = wid & 1;
    const int lr = lane & 15, lc = lane >> 4;
    const int ng = (tid & 15) * 8, kg = (tid >> 4) * 4;
    const int gg = ng >> 6, d8 = ng & 63;

    __half* x0h = (__half*)smem;
    uint16_t* tbl = (uint16_t*)(smem + L1_TBL);
    const uint32_t sbase = smem_u32(smem);
    const uint32_t ab0 = sbase + L1_A, bb0 = sbase + L1_B;
    const __half* x0_g = x0h + gg * FDIM * DDIM;

    for (int i = tid; i < 1536; i += THREADS) {
        int h = i / FDIM, m = i - h * FDIM;
        tbl[i] = (uint16_t)((h << 8) | m);
    }
    for (int i = tid; i < G * FDIM * DDIM; i += THREADS)
        x0h[i] = __float2half_rn(X0[(size_t)b0 * FDIM * DDIM + i]);

    float acc[2][8][4];
#pragma unroll
    for (int a = 0; a < 2; ++a)
#pragma unroll
        for (int b = 0; b < 8; ++b)
#pragma unroll
            for (int c = 0; c < 4; ++c) acc[a][b][c] = 0.f;

    auto genj_full = [&](uint32_t bbuf, int c0, int j) {
        const int k = kg + j;
        const uint32_t hm = tbl[c0 + k];
        const uint4 xa = *(const uint4*)(x0_g + (hm >> 8) * DDIM + d8);
        const uint4 xb = *(const uint4*)(x0_g + (hm & 255) * DDIM + d8);
        uint4 rv;
        rv.x = h2m(xa.x, xb.x); rv.y = h2m(xa.y, xb.y);
        rv.z = h2m(xa.z, xb.z); rv.w = h2m(xa.w, xb.w);
        asm volatile("st.shared.v4.b32 [%0], {%1,%2,%3,%4};"
            :: "r"(bbuf + SWZ256((uint32_t)(k * 256 + ng * 2))),
               "r"(rv.x), "r"(rv.y), "r"(rv.z), "r"(rv.w) : "memory");
    };
    auto genj_tail = [&](uint32_t bbuf, int c0, int j) {
        const int k = kg + j;
        const int c = c0 + k;
        uint4 rv = make_uint4(0u, 0u, 0u, 0u);
        if (c < C_) {
            const uint32_t hm = tbl[c];
            const uint4 xa = *(const uint4*)(x0_g + (hm >> 8) * DDIM + d8);
            const uint4 xb = *(const uint4*)(x0_g + (hm & 255) * DDIM + d8);
            rv.x = h2m(xa.x, xb.x); rv.y = h2m(xa.y, xb.y);
            rv.z = h2m(xa.z, xb.z); rv.w = h2m(xa.w, xb.w);
        }
        asm volatile("st.shared.v4.b32 [%0], {%1,%2,%3,%4};"
            :: "r"(bbuf + SWZ256((uint32_t)(k * 256 + ng * 2))),
               "r"(rv.x), "r"(rv.y), "r"(rv.z), "r"(rv.w) : "memory");
    };

    __syncthreads();   // x0h + tbl ready
    stage_w<CPAD_>(ab0, W, 0, tid);
#pragma unroll
    for (int j = 0; j < 4; ++j) genj_full(bb0, 0, j);             // tile 0
#pragma unroll
    for (int j = 0; j < 4; ++j) genj_full(bb0 + BS_SZ, KT, j);    // tile 1
    CP_WAIT0();
    __syncthreads();

    int bcur = 0;                 // t % 3
    for (int t = 0; t < NT; ++t) {
        const int tn = t + 1, t2 = t + 2;
        const bool dg = (t2 < NT);
        const bool tail = (t2 == NT - 1);
        const int c02 = t2 * KT;
        int b2 = bcur + 2; if (b2 >= 3) b2 -= 3;
        const uint32_t bb2 = bb0 + b2 * BS_SZ;
        const uint32_t abn = ab0 + (tn & 1) * AS_SZ;

        auto gen_part = [&](int kb) {
            if (kb == 0 && tn < NT) stage_w<CPAD_>(abn, W, tn * KT, tid);
            if (!dg) return;
            if (tail) genj_tail(bb2, c02, kb);
            else      genj_full(bb2, c02, kb);
        };

        mma_tile_fused(ab0 + (t & 1) * AS_SZ, bb0 + bcur * BS_SZ,
                       warp_m, warp_n, lr, lc, acc, gen_part);
        CP_WAIT0();
        __syncthreads();
        if (++bcur == 3) bcur = 0;
    }
    epilogue(acc, bias, Xout, out, 0, b0, warp_m, warp_n, lane);
}

// ---------------- Layers 2/3 ----------------
__global__ __launch_bounds__(THREADS, 2) void cin_l23(
    const float* __restrict__ X0, const __half* __restrict__ Xi,
    const __half* __restrict__ W,
    const float* __restrict__ bias, __half* __restrict__ Xout,
    float* __restrict__ out, int out_off)
{
    extern __shared__ char smem[];
    constexpr int CPAD_ = 4992, M_ = 128, NT = 78;   // 2 mb x 39 h

    const int tid = threadIdx.x, wid = tid >> 5, lane = tid & 31;
    const int b0 = blockIdx.x * G;
    const int warp_m = wid >> 1, warp_n = wid & 1;
    const int lr = lane & 15, lc = lane >> 4;
    const int ng = (tid & 15) * 8, kg = (tid >> 4) * 4;
    const int gg = ng >> 6, d8 = ng & 63;

    __half* xis = (__half*)smem;
    const uint32_t sbase = smem_u32(smem);
    const uint32_t ab0 = sbase + L23_A, bb0 = sbase + L23_B;
    const __half* xi_g = xis + gg * 8192;
    const float* x0_row = X0 + (size_t)(b0 + gg) * FDIM * DDIM + d8;

#pragma unroll
    for (int it = 0; it < 8; ++it) {
        const int idx = it * THREADS + tid;
        CP_ASYNC16(sbase + idx * 16, Xi + (size_t)b0 * ODIM * DDIM + idx * 8);
    }
    CP_COMMIT();

    float acc[2][8][4];
#pragma unroll
    for (int a = 0; a < 2; ++a)
#pragma unroll
        for (int b = 0; b < 8; ++b)
#pragma unroll
            for (int c = 0; c < 4; ++c) acc[a][b][c] = 0.f;

    auto x0ld = [&](int h, float4& f0, float4& f1) {
        f0 = __ldg((const float4*)(x0_row + h * DDIM));
        f1 = __ldg((const float4*)(x0_row + h * DDIM + 4));
    };

    auto genj = [&](uint32_t bbuf, const uint32_t* xw, int mbase, int j) {
        const int k = kg + j;
        const uint4 iv = *(const uint4*)(xi_g + (mbase + k) * DDIM + d8);
        uint4 rv;
        rv.x = h2m(xw[0], iv.x); rv.y = h2m(xw[1], iv.y);
        rv.z = h2m(xw[2], iv.z); rv.w = h2m(xw[3], iv.w);
        asm volatile("st.shared.v4.b32 [%0], {%1,%2,%3,%4};"
            :: "r"(bbuf + SWZ256((uint32_t)(k * 256 + ng * 2))),
               "r"(rv.x), "r"(rv.y), "r"(rv.z), "r"(rv.w) : "memory");
    };

    CP_WAIT0();        // xis resident
    __syncthreads();

    // prologue: gen tiles 0 (mb0,h0) and 1 (mb0,h1); stage A for tile 0
    stage_w<CPAD_>(ab0, W, 0, tid);
    {
        float4 f0, f1;
        x0ld(0, f0, f1);
        uint32_t xw[4] = { packh2(f0.x, f0.y), packh2(f0.z, f0.w),
                           packh2(f1.x, f1.y), packh2(f1.z, f1.w) };
#pragma unroll
        for (int j = 0; j < 4; ++j) genj(bb0, xw, 0, j);
        x0ld(1, f0, f1);
        uint32_t xw1[4] = { packh2(f0.x, f0.y), packh2(f0.z, f0.w),
                            packh2(f1.x, f1.y), packh2(f1.z, f1.w) };
#pragma unroll
        for (int j = 0; j < 4; ++j) genj(bb0 + BS_SZ, xw1, 0, j);
    }
    float4 xf0, xf1;
    x0ld(2, xf0, xf1);       // row for tile 2 (gen at iter 0)
    CP_WAIT0();
    __syncthreads();

    int bcur = 0;
    int t = 0;
    for (int mb = 0; mb < 2; ++mb) {
        for (int h = 0; h < FDIM; ++h, ++t) {
            const int tn = t + 1, t2 = t + 2;
            const bool dg = (t2 < NT);
            int h1 = h + 1, mb1 = mb; if (h1 >= FDIM) { h1 -= FDIM; ++mb1; }
            int h2 = h + 2, mb2 = mb; if (h2 >= FDIM) { h2 -= FDIM; ++mb2; }
            int b2 = bcur + 2; if (b2 >= 3) b2 -= 3;
            const uint32_t bb2 = bb0 + b2 * BS_SZ;
            const uint32_t abn = ab0 + (tn & 1) * AS_SZ;
            const uint32_t xw[4] = { packh2(xf0.x, xf0.y), packh2(xf0.z, xf0.w),
                                     packh2(xf1.x, xf1.y), packh2(xf1.z, xf1.w) };
            if (t + 3 < NT) {
                int h3 = h + 3; if (h3 >= FDIM) h3 -= FDIM;
                x0ld(h3, xf0, xf1);
            }
            const int mbase2 = mb2 * KT;

            auto gen_part = [&](int kb) {
                if (kb == 0 && tn < NT) stage_w<CPAD_>(abn, W, h1 * M_ + mb1 * KT, tid);
                if (!dg) return;
                genj(bb2, xw, mbase2, kb);
            };

            mma_tile_fused(ab0 + (t & 1) * AS_SZ, bb0 + bcur * BS_SZ,
                           warp_m, warp_n, lr, lc, acc, gen_part);
            CP_WAIT0();
            __syncthreads();
            if (++bcur == 3) bcur = 0;
        }
    }
    epilogue(acc, bias, Xout, out, out_off, b0, warp_m, warp_n, lane);
}

// ---------------- launch ----------------
extern "C" void kernel_launch(void* const* d_in, const int* in_sizes, int n_in,
                              void* d_out, int out_size)
{
    const float* X0 = (const float*)d_in[0];
    const float* W1 = (const float*)d_in[1];
    const float* b1 = (const float*)d_in[2];
    const float* W2 = (const float*)d_in[3];
    const float* b2 = (const float*)d_in[4];
    const float* W3 = (const float*)d_in[5];
    const float* b3 = (const float*)d_in[6];
    float* out = (float*)d_out;

    __half *X1p, *X2p, *W1h, *W2h, *W3h;
    cudaGetSymbolAddress((void**)&X1p, g_X1);
    cudaGetSymbolAddress((void**)&X2p, g_X2);
    cudaGetSymbolAddress((void**)&W1h, g_W1);
    cudaGetSymbolAddress((void**)&W2h, g_W2);
    cudaGetSymbolAddress((void**)&W3h, g_W3);

    cudaFuncSetAttribute(cin_l1,  cudaFuncAttributeMaxDynamicSharedMemorySize, SMEM_L1);
    cudaFuncSetAttribute(cin_l23, cudaFuncAttributeMaxDynamicSharedMemorySize, SMEM_L23);

    conv_w_kernel<<<(ODIM * 1536 + 255) / 256, 256>>>(W1, W1h, 1521, 1536);
    conv_w_kernel<<<(ODIM * 4992 + 255) / 256, 256>>>(W2, W2h, 4992, 4992);
    conv_w_kernel<<<(ODIM * 4992 + 255) / 256, 256>>>(W3, W3h, 4992, 4992);

    cin_l1 <<<BATCH / G, THREADS, SMEM_L1 >>>(X0, W1h, b1, X1p, out);
    cin_l23<<<BATCH / G, THREADS, SMEM_L23>>>(X0, X1p, W2h, b2, X2p, out, 128);
    cin_l23<<<BATCH / G, THREADS, SMEM_L23>>>(X0, X2p, W3h, b3, nullptr, out, 256);
}